// round 6
// baseline (speedup 1.0000x reference)
#include <cuda_runtime.h>

// ---------------------------------------------------------------------------
// Seq2Seq VAE (encoder LSTM -> reparam -> autoregressive decoder LSTM)
// B=1024, T_src=1024, I=64, H=512, L=64, O=1, tgt_len derived from out_size.
//
// Strategy: batch rows are independent through the whole recurrence, so split
// B across 128 persistent blocks (8 rows each). No grid sync. Weights are
// pre-transposed into a [k][col] layout where each thread's 8 gate columns
// (i,f,g,o pairs for its 2 hidden features) are contiguous (coalesced LDG.128).
// Inner product uses packed fp32 FMA (fma.rn.f32x2, sm_103a) for 2x fp32 rate.
// h is kept in SMEM as duplicated f32x2 pairs; c lives in registers.
// Weight stream prefetched 2 k-pairs ahead (~270 cyc) to cover L2 latency.
// ---------------------------------------------------------------------------

#define B_    1024
#define TSRC  1024
#define I_    64
#define H_    512
#define L_    64
#define G4    2048   // 4*H
#define KE    576    // I + H (encoder fused K)
#define KD    512    // decoder K (x handled as rank-1 bias fold)
#define MB    8      // batch rows per block
#define NT    256    // threads per block (= H/2 feature pairs)
#define NBLK  (B_ / MB)

// Scratch (allowed: __device__ globals)
__device__ float g_WencT[KE * G4];   // 4.7 MB
__device__ float g_WdecT[KD * G4];   // 4.2 MB

union U64  { unsigned long long u; float2 f; };
union U128 { float4 v; unsigned long long u[2]; float f[4]; };

__device__ __forceinline__ unsigned long long ffma2(unsigned long long a,
                                                    unsigned long long b,
                                                    unsigned long long c) {
    unsigned long long d;
    asm("fma.rn.f32x2 %0, %1, %2, %3;" : "=l"(d) : "l"(a), "l"(b), "l"(c));
    return d;
}
__device__ __forceinline__ float sigf(float x)  { return 1.0f / (1.0f + __expf(-x)); }
__device__ __forceinline__ float tanh_f(float x){ return 2.0f / (1.0f + __expf(-2.0f * x)) - 1.0f; }

// Accumulate acc[m][g] (f32x2 pairs) += shA[m][k] * Wt[k][p*8 + g*2 + {0,1}]
// Wt row = 2048 floats. Thread p reads cols [8p, 8p+8) = 2x float4 per k.
// 2-deep software pipeline: at pair i, issue loads for pair i+2 (~270 cyc cover
// vs L2 latency 234-262 cyc).
template <int K>
__device__ __forceinline__ void gemm_acc(const float* __restrict__ Wt,
                                         const float2 (*__restrict__ shA)[592],
                                         int p, unsigned long long acc[MB][4]) {
    const float4* wp = reinterpret_cast<const float4*>(Wt) + p * 2;  // row stride 512 float4
    constexpr int P = K / 2;   // k-pairs
    U128 buf[2][4];
#pragma unroll
    for (int s = 0; s < 2; s++) {
        buf[s][0].v = wp[(size_t)(2 * s) * 512];
        buf[s][1].v = wp[(size_t)(2 * s) * 512 + 1];
        buf[s][2].v = wp[(size_t)(2 * s + 1) * 512];
        buf[s][3].v = wp[(size_t)(2 * s + 1) * 512 + 1];
    }
#pragma unroll 2
    for (int i = 0; i < P; i++) {
        const int cur = i & 1;
        const int ip = (i + 2 < P) ? (i + 2) : 0;
        U128 n0, n1, n2, n3;
        n0.v = wp[(size_t)(2 * ip) * 512];
        n1.v = wp[(size_t)(2 * ip) * 512 + 1];
        n2.v = wp[(size_t)(2 * ip + 1) * 512];
        n3.v = wp[(size_t)(2 * ip + 1) * 512 + 1];
        const int k = 2 * i;
#pragma unroll
        for (int m = 0; m < MB; m++) {
            U128 a; a.v = *reinterpret_cast<const float4*>(&shA[m][k]);  // dup pairs k, k+1
            acc[m][0] = ffma2(a.u[0], buf[cur][0].u[0], acc[m][0]);
            acc[m][1] = ffma2(a.u[0], buf[cur][0].u[1], acc[m][1]);
            acc[m][2] = ffma2(a.u[0], buf[cur][1].u[0], acc[m][2]);
            acc[m][3] = ffma2(a.u[0], buf[cur][1].u[1], acc[m][3]);
            acc[m][0] = ffma2(a.u[1], buf[cur][2].u[0], acc[m][0]);
            acc[m][1] = ffma2(a.u[1], buf[cur][2].u[1], acc[m][1]);
            acc[m][2] = ffma2(a.u[1], buf[cur][3].u[0], acc[m][2]);
            acc[m][3] = ffma2(a.u[1], buf[cur][3].u[1], acc[m][3]);
        }
        buf[cur][0] = n0; buf[cur][1] = n1; buf[cur][2] = n2; buf[cur][3] = n3;
    }
}

// Pack weights: WT[k][p*8 + g*2 + q] = W[g*512 + 2p + q][k]  (k-major, coalesced reads)
__global__ void pack_enc(const float* __restrict__ Wih, const float* __restrict__ Whh) {
    int idx = blockIdx.x * blockDim.x + threadIdx.x;
    if (idx >= KE * G4) return;
    int k = idx >> 11, c = idx & 2047;
    int pp = c >> 3, g = (c >> 1) & 3, q = c & 1;
    int n = g * H_ + 2 * pp + q;
    g_WencT[idx] = (k < I_) ? Wih[n * I_ + k] : Whh[n * H_ + (k - I_)];
}
__global__ void pack_dec(const float* __restrict__ Whh) {
    int idx = blockIdx.x * blockDim.x + threadIdx.x;
    if (idx >= KD * G4) return;
    int k = idx >> 11, c = idx & 2047;
    int pp = c >> 3, g = (c >> 1) & 3, q = c & 1;
    int n = g * H_ + 2 * pp + q;
    g_WdecT[idx] = Whh[n * H_ + k];
}

__global__ void __launch_bounds__(NT, 1)
vae_main(const float* __restrict__ src, const float* __restrict__ eps,
         const float* __restrict__ b_e,
         const float* __restrict__ W_mu, const float* __restrict__ b_mu,
         const float* __restrict__ W_lv, const float* __restrict__ b_lv,
         const float* __restrict__ W_zh, const float* __restrict__ b_zh,
         const float* __restrict__ W_zc, const float* __restrict__ b_zc,
         const float* __restrict__ W_ih_d, const float* __restrict__ b_d,
         const float* __restrict__ W_out, const float* __restrict__ b_out,
         float* __restrict__ out, int T, int write_mulv) {
    // a-buffer: duplicated f32x2 activations. enc: [0,64)=x_t, [64,576)=h. dec: [0,512)=h.
    __shared__ __align__(16) float2 shA[MB][592];
    __shared__ float  shZ[MB][L_];
    __shared__ float  shRed[8][MB];
    __shared__ float  shX[MB];

    const int tid  = threadIdx.x;
    const int lane = tid & 31, warp = tid >> 5;
    const int p    = tid;             // feature pair: features 2p, 2p+1
    const int m0   = blockIdx.x * MB;

    // Per-thread constant preloads (pairs for gates i,f,g,o)
    U64 be[4], bd[4], wihd[4];
#pragma unroll
    for (int g = 0; g < 4; g++) {
        be[g].f   = *reinterpret_cast<const float2*>(&b_e[g * H_ + 2 * p]);
        bd[g].f   = *reinterpret_cast<const float2*>(&b_d[g * H_ + 2 * p]);
        wihd[g].f = *reinterpret_cast<const float2*>(&W_ih_d[g * H_ + 2 * p]);
    }
    float2 wo = *reinterpret_cast<const float2*>(&W_out[2 * p]);
    float  bo = b_out[0];

    // h0 = c0 = 0
    for (int e = tid; e < MB * KE; e += NT) {
        int m = e / KE, k = e % KE;
        shA[m][k] = make_float2(0.f, 0.f);
    }
    float2 cst[MB];
#pragma unroll
    for (int m = 0; m < MB; m++) cst[m] = make_float2(0.f, 0.f);
    __syncthreads();

    // ---------------- Encoder ----------------
    for (int t = 0; t < TSRC; t++) {
        {   // load x_t as dup pairs: 8 rows x 64 feats, 2 per thread
            int m = tid >> 5;
            int i = (tid & 31) * 2;
            float2 v = *reinterpret_cast<const float2*>(
                &src[((size_t)(m0 + m) * TSRC + t) * I_ + i]);
            shA[m][i]     = make_float2(v.x, v.x);
            shA[m][i + 1] = make_float2(v.y, v.y);
        }
        __syncthreads();   // x(t) and h(t-1) writes all visible

        unsigned long long acc[MB][4];
#pragma unroll
        for (int m = 0; m < MB; m++) {
            acc[m][0] = be[0].u; acc[m][1] = be[1].u;
            acc[m][2] = be[2].u; acc[m][3] = be[3].u;
        }
        gemm_acc<KE>(g_WencT, shA, p, acc);
        __syncthreads();   // all reads of shA done before h overwrite

#pragma unroll
        for (int m = 0; m < MB; m++) {
            U64 gi, gf, gg, go;
            gi.u = acc[m][0]; gf.u = acc[m][1]; gg.u = acc[m][2]; go.u = acc[m][3];
            float cx = sigf(gf.f.x) * cst[m].x + sigf(gi.f.x) * tanh_f(gg.f.x);
            float cy = sigf(gf.f.y) * cst[m].y + sigf(gi.f.y) * tanh_f(gg.f.y);
            cst[m] = make_float2(cx, cy);
            float hx = sigf(go.f.x) * tanh_f(cx);
            float hy = sigf(go.f.y) * tanh_f(cy);
            shA[m][I_ + 2 * p]     = make_float2(hx, hx);
            shA[m][I_ + 2 * p + 1] = make_float2(hy, hy);
        }
        // next iter: x-load writes disjoint region; the sync after it orders h too
    }
    __syncthreads();

    // ---------------- mu / logvar / z ----------------
    for (int r = 0; r < 2; r++) {
        int idx = tid + r * NT;             // 512 tasks (m,l)
        int m = idx >> 6, l = idx & 63;
        float smu = b_mu[l], slv = b_lv[l];
        for (int j = 0; j < H_; j += 4) {
            float4 wm = *reinterpret_cast<const float4*>(&W_mu[l * H_ + j]);
            float4 wl = *reinterpret_cast<const float4*>(&W_lv[l * H_ + j]);
            float h0 = shA[m][I_ + j].x,     h1 = shA[m][I_ + j + 1].x;
            float h2 = shA[m][I_ + j + 2].x, h3 = shA[m][I_ + j + 3].x;
            smu += h0 * wm.x + h1 * wm.y + h2 * wm.z + h3 * wm.w;
            slv += h0 * wl.x + h1 * wl.y + h2 * wl.z + h3 * wl.w;
        }
        float ev = eps[(size_t)(m0 + m) * L_ + l];
        float z  = smu + ev * __expf(0.5f * slv);
        shZ[m][l] = z;
        if (write_mulv) {
            size_t mu_off = (size_t)B_ * T;
            out[mu_off + (size_t)(m0 + m) * L_ + l] = smu;
            out[mu_off + (size_t)B_ * L_ + (size_t)(m0 + m) * L_ + l] = slv;
        }
    }
    __syncthreads();

    // ---------------- decoder init: h_d = tanh(zWzh+b), c_d = tanh(zWzc+b) ----------------
    {
        int j0 = 2 * p, j1 = 2 * p + 1;
        for (int m = 0; m < MB; m++) {
            float a0 = b_zh[j0], a1 = b_zh[j1];
            float c0 = b_zc[j0], c1 = b_zc[j1];
            for (int l = 0; l < L_; l++) {
                float zv = shZ[m][l];
                a0 += zv * W_zh[j0 * L_ + l];
                a1 += zv * W_zh[j1 * L_ + l];
                c0 += zv * W_zc[j0 * L_ + l];
                c1 += zv * W_zc[j1 * L_ + l];
            }
            float hx = tanh_f(a0), hy = tanh_f(a1);
            shA[m][j0] = make_float2(hx, hx);
            shA[m][j1] = make_float2(hy, hy);
            cst[m] = make_float2(tanh_f(c0), tanh_f(c1));
        }
        if (tid < MB) shX[tid] = 0.f;   // x_0 = 0
    }
    __syncthreads();

    // ---------------- Decoder (autoregressive) ----------------
    for (int t = 0; t < T; t++) {
        unsigned long long acc[MB][4];
#pragma unroll
        for (int m = 0; m < MB; m++) {
            float xv = shX[m];
            U64 xd; xd.f = make_float2(xv, xv);
            acc[m][0] = ffma2(xd.u, wihd[0].u, bd[0].u);
            acc[m][1] = ffma2(xd.u, wihd[1].u, bd[1].u);
            acc[m][2] = ffma2(xd.u, wihd[2].u, bd[2].u);
            acc[m][3] = ffma2(xd.u, wihd[3].u, bd[3].u);
        }
        gemm_acc<KD>(g_WdecT, shA, p, acc);
        __syncthreads();   // reads done before h overwrite

        float pm[MB];
#pragma unroll
        for (int m = 0; m < MB; m++) {
            U64 gi, gf, gg, go;
            gi.u = acc[m][0]; gf.u = acc[m][1]; gg.u = acc[m][2]; go.u = acc[m][3];
            float cx = sigf(gf.f.x) * cst[m].x + sigf(gi.f.x) * tanh_f(gg.f.x);
            float cy = sigf(gf.f.y) * cst[m].y + sigf(gi.f.y) * tanh_f(gg.f.y);
            cst[m] = make_float2(cx, cy);
            float hx = sigf(go.f.x) * tanh_f(cx);
            float hy = sigf(go.f.y) * tanh_f(cy);
            shA[m][2 * p]     = make_float2(hx, hx);
            shA[m][2 * p + 1] = make_float2(hy, hy);
            pm[m] = hx * wo.x + hy * wo.y;
        }
        // out_t = h_new . W_out + b_out : block reduction over 512 features
#pragma unroll
        for (int m = 0; m < MB; m++) {
            float s = pm[m];
            s += __shfl_xor_sync(0xffffffffu, s, 16);
            s += __shfl_xor_sync(0xffffffffu, s, 8);
            s += __shfl_xor_sync(0xffffffffu, s, 4);
            s += __shfl_xor_sync(0xffffffffu, s, 2);
            s += __shfl_xor_sync(0xffffffffu, s, 1);
            if (lane == 0) shRed[warp][m] = s;
        }
        __syncthreads();
        if (tid < MB) {
            float s = bo;
#pragma unroll
            for (int w = 0; w < 8; w++) s += shRed[w][tid];
            out[(size_t)(m0 + tid) * T + t] = s;   // recon[b][t][0]
            shX[tid] = s;                          // feed back
        }
        __syncthreads();
    }
}

extern "C" void kernel_launch(void* const* d_in, const int* in_sizes, int n_in,
                              void* d_out, int out_size) {
    const float* src    = (const float*)d_in[0];
    const float* eps    = (const float*)d_in[1];
    // d_in[2] = tgt_len (int32 on device); length derived from out_size instead
    const float* W_ih_e = (const float*)d_in[3];
    const float* W_hh_e = (const float*)d_in[4];
    const float* b_e    = (const float*)d_in[5];
    const float* W_mu   = (const float*)d_in[6];
    const float* b_mu   = (const float*)d_in[7];
    const float* W_lv   = (const float*)d_in[8];
    const float* b_lv   = (const float*)d_in[9];
    const float* W_zh   = (const float*)d_in[10];
    const float* b_zh   = (const float*)d_in[11];
    const float* W_zc   = (const float*)d_in[12];
    const float* b_zc   = (const float*)d_in[13];
    const float* W_ih_d = (const float*)d_in[14];
    const float* W_hh_d = (const float*)d_in[15];
    const float* b_d    = (const float*)d_in[16];
    const float* W_out  = (const float*)d_in[17];
    const float* b_out  = (const float*)d_in[18];
    float* out = (float*)d_out;

    // out = [recon (B*T), mu (B*L), logvar (B*L)] flattened (preferred),
    // or recon-only if out_size doesn't include the mu/logvar tail.
    long long os = out_size;
    int write_mulv = 1;
    long long Tll = (os - (long long)2 * B_ * L_) / B_;
    if (Tll <= 0 || (Tll * B_ + (long long)2 * B_ * L_) != os) {
        Tll = os / B_;
        write_mulv = 0;
    }
    int T = (int)Tll;

    pack_enc<<<(KE * G4 + 255) / 256, 256>>>(W_ih_e, W_hh_e);
    pack_dec<<<(KD * G4 + 255) / 256, 256>>>(W_hh_d);
    vae_main<<<NBLK, NT>>>(src, eps, b_e, W_mu, b_mu, W_lv, b_lv,
                           W_zh, b_zh, W_zc, b_zc, W_ih_d, b_d, W_out, b_out,
                           out, T, write_mulv);
}

// round 7
// speedup vs baseline: 1.0053x; 1.0053x over previous
#include <cuda_runtime.h>
#include <cuda_fp16.h>

// ---------------------------------------------------------------------------
// Seq2Seq VAE (encoder LSTM -> reparam -> autoregressive decoder LSTM)
// B=1024, T_src=1024, I=64, H=512, L=64, O=1, tgt_len derived from out_size.
//
// Round-6 baseline passed at 125.9 ms, ~79% of the L2 delivery ceiling
// (600 MB/step of fp32 weights). This round halves the weight stream: the two
// big recurrent matrices are packed to fp16 (activations/accumulation stay
// fp32 via half2->float2 convert + fma.rn.f32x2). New floor = fp32 FMA pipe
// (~38 us/step); L2 drops to ~24 us/step.
// ---------------------------------------------------------------------------

#define B_    1024
#define TSRC  1024
#define I_    64
#define H_    512
#define L_    64
#define G4    2048   // 4*H
#define KE    576    // I + H (encoder fused K)
#define KD    512    // decoder K (x handled as rank-1 bias fold)
#define MB    8      // batch rows per block
#define NT    256    // threads per block (= H/2 feature pairs)
#define NBLK  (B_ / MB)

// Scratch (allowed: __device__ globals). fp16 weights, uint4-aligned.
__device__ uint4 g_WencH[KE * G4 / 8];   // 2.36 MB
__device__ uint4 g_WdecH[KD * G4 / 8];   // 2.10 MB

union U64  { unsigned long long u; float2 f; };
union U128 { float4 v; unsigned long long u[2]; float f[4]; };
union UH   { uint4 u4; __half2 h2[4]; };

__device__ __forceinline__ unsigned long long ffma2(unsigned long long a,
                                                    unsigned long long b,
                                                    unsigned long long c) {
    unsigned long long d;
    asm("fma.rn.f32x2 %0, %1, %2, %3;" : "=l"(d) : "l"(a), "l"(b), "l"(c));
    return d;
}
__device__ __forceinline__ float sigf(float x)  { return 1.0f / (1.0f + __expf(-x)); }
__device__ __forceinline__ float tanh_f(float x){ return 2.0f / (1.0f + __expf(-2.0f * x)) - 1.0f; }

// Accumulate acc[m][g] (f32x2 pairs) += shA[m][k] * W[k][p*8 + g*2 + {0,1}]
// W row = 2048 fp16 = 256 uint4. Thread p reads cols [8p,8p+8) = 1 uint4/k.
// 2-deep software pipeline: at pair i, issue loads for pair i+2 (~270+ cyc
// cover vs L2 latency 234-262 cyc). Convert 16 halfs once per k-pair, then
// 64 ffma2 (8 per m x 8 m) — cvt sits on alu pipe under the fma shadow.
template <int K>
__device__ __forceinline__ void gemm_acc_h(const uint4* __restrict__ Wt,
                                           const float2 (*__restrict__ shA)[592],
                                           int p, unsigned long long acc[MB][4]) {
    const uint4* wp = Wt + p;            // row stride 256 uint4
    constexpr int P = K / 2;             // k-pairs
    UH buf[2][2];
#pragma unroll
    for (int s = 0; s < 2; s++) {
        buf[s][0].u4 = wp[(size_t)(2 * s) * 256];
        buf[s][1].u4 = wp[(size_t)(2 * s + 1) * 256];
    }
#pragma unroll 2
    for (int i = 0; i < P; i++) {
        const int cur = i & 1;
        const int ip = (i + 2 < P) ? (i + 2) : 0;
        uint4 n0 = wp[(size_t)(2 * ip) * 256];
        uint4 n1 = wp[(size_t)(2 * ip + 1) * 256];

        // fp16 -> fp32 pairs for the 4 gate column-pairs of rows k, k+1
        U64 w0[4], w1[4];
#pragma unroll
        for (int g = 0; g < 4; g++) {
            w0[g].f = __half22float2(buf[cur][0].h2[g]);
            w1[g].f = __half22float2(buf[cur][1].h2[g]);
        }
        const int k = 2 * i;
#pragma unroll
        for (int m = 0; m < MB; m++) {
            U128 a; a.v = *reinterpret_cast<const float4*>(&shA[m][k]);  // dup pairs k, k+1
            acc[m][0] = ffma2(a.u[0], w0[0].u, acc[m][0]);
            acc[m][1] = ffma2(a.u[0], w0[1].u, acc[m][1]);
            acc[m][2] = ffma2(a.u[0], w0[2].u, acc[m][2]);
            acc[m][3] = ffma2(a.u[0], w0[3].u, acc[m][3]);
            acc[m][0] = ffma2(a.u[1], w1[0].u, acc[m][0]);
            acc[m][1] = ffma2(a.u[1], w1[1].u, acc[m][1]);
            acc[m][2] = ffma2(a.u[1], w1[2].u, acc[m][2]);
            acc[m][3] = ffma2(a.u[1], w1[3].u, acc[m][3]);
        }
        buf[cur][0].u4 = n0;
        buf[cur][1].u4 = n1;
    }
}

// Pack weights to fp16: WH[k][p*8 + g*2 + q] = (half)W[g*512 + 2p + q][k]
__global__ void pack_enc(const float* __restrict__ Wih, const float* __restrict__ Whh) {
    int idx = blockIdx.x * blockDim.x + threadIdx.x;
    if (idx >= KE * G4) return;
    int k = idx >> 11, c = idx & 2047;
    int pp = c >> 3, g = (c >> 1) & 3, q = c & 1;
    int n = g * H_ + 2 * pp + q;
    float v = (k < I_) ? Wih[n * I_ + k] : Whh[n * H_ + (k - I_)];
    reinterpret_cast<__half*>(g_WencH)[idx] = __float2half_rn(v);
}
__global__ void pack_dec(const float* __restrict__ Whh) {
    int idx = blockIdx.x * blockDim.x + threadIdx.x;
    if (idx >= KD * G4) return;
    int k = idx >> 11, c = idx & 2047;
    int pp = c >> 3, g = (c >> 1) & 3, q = c & 1;
    int n = g * H_ + 2 * pp + q;
    reinterpret_cast<__half*>(g_WdecH)[idx] = __float2half_rn(Whh[n * H_ + k]);
}

__global__ void __launch_bounds__(NT, 1)
vae_main(const float* __restrict__ src, const float* __restrict__ eps,
         const float* __restrict__ b_e,
         const float* __restrict__ W_mu, const float* __restrict__ b_mu,
         const float* __restrict__ W_lv, const float* __restrict__ b_lv,
         const float* __restrict__ W_zh, const float* __restrict__ b_zh,
         const float* __restrict__ W_zc, const float* __restrict__ b_zc,
         const float* __restrict__ W_ih_d, const float* __restrict__ b_d,
         const float* __restrict__ W_out, const float* __restrict__ b_out,
         float* __restrict__ out, int T, int write_mulv) {
    // a-buffer: duplicated f32x2 activations. enc: [0,64)=x_t, [64,576)=h. dec: [0,512)=h.
    __shared__ __align__(16) float2 shA[MB][592];
    __shared__ float  shZ[MB][L_];
    __shared__ float  shRed[8][MB];
    __shared__ float  shX[MB];

    const int tid  = threadIdx.x;
    const int lane = tid & 31, warp = tid >> 5;
    const int p    = tid;             // feature pair: features 2p, 2p+1
    const int m0   = blockIdx.x * MB;

    // Per-thread constant preloads (pairs for gates i,f,g,o)
    U64 be[4], bd[4], wihd[4];
#pragma unroll
    for (int g = 0; g < 4; g++) {
        be[g].f   = *reinterpret_cast<const float2*>(&b_e[g * H_ + 2 * p]);
        bd[g].f   = *reinterpret_cast<const float2*>(&b_d[g * H_ + 2 * p]);
        wihd[g].f = *reinterpret_cast<const float2*>(&W_ih_d[g * H_ + 2 * p]);
    }
    float2 wo = *reinterpret_cast<const float2*>(&W_out[2 * p]);
    float  bo = b_out[0];

    // h0 = c0 = 0
    for (int e = tid; e < MB * KE; e += NT) {
        int m = e / KE, k = e % KE;
        shA[m][k] = make_float2(0.f, 0.f);
    }
    float2 cst[MB];
#pragma unroll
    for (int m = 0; m < MB; m++) cst[m] = make_float2(0.f, 0.f);
    __syncthreads();

    // ---------------- Encoder ----------------
    for (int t = 0; t < TSRC; t++) {
        {   // load x_t as dup pairs: 8 rows x 64 feats, 2 per thread
            int m = tid >> 5;
            int i = (tid & 31) * 2;
            float2 v = *reinterpret_cast<const float2*>(
                &src[((size_t)(m0 + m) * TSRC + t) * I_ + i]);
            shA[m][i]     = make_float2(v.x, v.x);
            shA[m][i + 1] = make_float2(v.y, v.y);
        }
        __syncthreads();   // x(t) and h(t-1) writes all visible

        unsigned long long acc[MB][4];
#pragma unroll
        for (int m = 0; m < MB; m++) {
            acc[m][0] = be[0].u; acc[m][1] = be[1].u;
            acc[m][2] = be[2].u; acc[m][3] = be[3].u;
        }
        gemm_acc_h<KE>(g_WencH, shA, p, acc);
        __syncthreads();   // all reads of shA done before h overwrite

#pragma unroll
        for (int m = 0; m < MB; m++) {
            U64 gi, gf, gg, go;
            gi.u = acc[m][0]; gf.u = acc[m][1]; gg.u = acc[m][2]; go.u = acc[m][3];
            float cx = sigf(gf.f.x) * cst[m].x + sigf(gi.f.x) * tanh_f(gg.f.x);
            float cy = sigf(gf.f.y) * cst[m].y + sigf(gi.f.y) * tanh_f(gg.f.y);
            cst[m] = make_float2(cx, cy);
            float hx = sigf(go.f.x) * tanh_f(cx);
            float hy = sigf(go.f.y) * tanh_f(cy);
            shA[m][I_ + 2 * p]     = make_float2(hx, hx);
            shA[m][I_ + 2 * p + 1] = make_float2(hy, hy);
        }
        // next iter: x-load writes disjoint region; the sync after it orders h too
    }
    __syncthreads();

    // ---------------- mu / logvar / z ----------------
    for (int r = 0; r < 2; r++) {
        int idx = tid + r * NT;             // 512 tasks (m,l)
        int m = idx >> 6, l = idx & 63;
        float smu = b_mu[l], slv = b_lv[l];
        for (int j = 0; j < H_; j += 4) {
            float4 wm = *reinterpret_cast<const float4*>(&W_mu[l * H_ + j]);
            float4 wl = *reinterpret_cast<const float4*>(&W_lv[l * H_ + j]);
            float h0 = shA[m][I_ + j].x,     h1 = shA[m][I_ + j + 1].x;
            float h2 = shA[m][I_ + j + 2].x, h3 = shA[m][I_ + j + 3].x;
            smu += h0 * wm.x + h1 * wm.y + h2 * wm.z + h3 * wm.w;
            slv += h0 * wl.x + h1 * wl.y + h2 * wl.z + h3 * wl.w;
        }
        float ev = eps[(size_t)(m0 + m) * L_ + l];
        float z  = smu + ev * __expf(0.5f * slv);
        shZ[m][l] = z;
        if (write_mulv) {
            size_t mu_off = (size_t)B_ * T;
            out[mu_off + (size_t)(m0 + m) * L_ + l] = smu;
            out[mu_off + (size_t)B_ * L_ + (size_t)(m0 + m) * L_ + l] = slv;
        }
    }
    __syncthreads();

    // ---------------- decoder init: h_d = tanh(zWzh+b), c_d = tanh(zWzc+b) ----------------
    {
        int j0 = 2 * p, j1 = 2 * p + 1;
        for (int m = 0; m < MB; m++) {
            float a0 = b_zh[j0], a1 = b_zh[j1];
            float c0 = b_zc[j0], c1 = b_zc[j1];
            for (int l = 0; l < L_; l++) {
                float zv = shZ[m][l];
                a0 += zv * W_zh[j0 * L_ + l];
                a1 += zv * W_zh[j1 * L_ + l];
                c0 += zv * W_zc[j0 * L_ + l];
                c1 += zv * W_zc[j1 * L_ + l];
            }
            float hx = tanh_f(a0), hy = tanh_f(a1);
            shA[m][j0] = make_float2(hx, hx);
            shA[m][j1] = make_float2(hy, hy);
            cst[m] = make_float2(tanh_f(c0), tanh_f(c1));
        }
        if (tid < MB) shX[tid] = 0.f;   // x_0 = 0
    }
    __syncthreads();

    // ---------------- Decoder (autoregressive) ----------------
    for (int t = 0; t < T; t++) {
        unsigned long long acc[MB][4];
#pragma unroll
        for (int m = 0; m < MB; m++) {
            float xv = shX[m];
            U64 xd; xd.f = make_float2(xv, xv);
            acc[m][0] = ffma2(xd.u, wihd[0].u, bd[0].u);
            acc[m][1] = ffma2(xd.u, wihd[1].u, bd[1].u);
            acc[m][2] = ffma2(xd.u, wihd[2].u, bd[2].u);
            acc[m][3] = ffma2(xd.u, wihd[3].u, bd[3].u);
        }
        gemm_acc_h<KD>(g_WdecH, shA, p, acc);
        __syncthreads();   // reads done before h overwrite

        float pm[MB];
#pragma unroll
        for (int m = 0; m < MB; m++) {
            U64 gi, gf, gg, go;
            gi.u = acc[m][0]; gf.u = acc[m][1]; gg.u = acc[m][2]; go.u = acc[m][3];
            float cx = sigf(gf.f.x) * cst[m].x + sigf(gi.f.x) * tanh_f(gg.f.x);
            float cy = sigf(gf.f.y) * cst[m].y + sigf(gi.f.y) * tanh_f(gg.f.y);
            cst[m] = make_float2(cx, cy);
            float hx = sigf(go.f.x) * tanh_f(cx);
            float hy = sigf(go.f.y) * tanh_f(cy);
            shA[m][2 * p]     = make_float2(hx, hx);
            shA[m][2 * p + 1] = make_float2(hy, hy);
            pm[m] = hx * wo.x + hy * wo.y;
        }
        // out_t = h_new . W_out + b_out : block reduction over 512 features
#pragma unroll
        for (int m = 0; m < MB; m++) {
            float s = pm[m];
            s += __shfl_xor_sync(0xffffffffu, s, 16);
            s += __shfl_xor_sync(0xffffffffu, s, 8);
            s += __shfl_xor_sync(0xffffffffu, s, 4);
            s += __shfl_xor_sync(0xffffffffu, s, 2);
            s += __shfl_xor_sync(0xffffffffu, s, 1);
            if (lane == 0) shRed[warp][m] = s;
        }
        __syncthreads();
        if (tid < MB) {
            float s = bo;
#pragma unroll
            for (int w = 0; w < 8; w++) s += shRed[w][tid];
            out[(size_t)(m0 + tid) * T + t] = s;   // recon[b][t][0]
            shX[tid] = s;                          // feed back
        }
        __syncthreads();
    }
}

extern "C" void kernel_launch(void* const* d_in, const int* in_sizes, int n_in,
                              void* d_out, int out_size) {
    const float* src    = (const float*)d_in[0];
    const float* eps    = (const float*)d_in[1];
    // d_in[2] = tgt_len (int32 on device); length derived from out_size instead
    const float* W_ih_e = (const float*)d_in[3];
    const float* W_hh_e = (const float*)d_in[4];
    const float* b_e    = (const float*)d_in[5];
    const float* W_mu   = (const float*)d_in[6];
    const float* b_mu   = (const float*)d_in[7];
    const float* W_lv   = (const float*)d_in[8];
    const float* b_lv   = (const float*)d_in[9];
    const float* W_zh   = (const float*)d_in[10];
    const float* b_zh   = (const float*)d_in[11];
    const float* W_zc   = (const float*)d_in[12];
    const float* b_zc   = (const float*)d_in[13];
    const float* W_ih_d = (const float*)d_in[14];
    const float* W_hh_d = (const float*)d_in[15];
    const float* b_d    = (const float*)d_in[16];
    const float* W_out  = (const float*)d_in[17];
    const float* b_out  = (const float*)d_in[18];
    float* out = (float*)d_out;

    // out = [recon (B*T), mu (B*L), logvar (B*L)] flattened (preferred),
    // or recon-only if out_size doesn't include the mu/logvar tail.
    long long os = out_size;
    int write_mulv = 1;
    long long Tll = (os - (long long)2 * B_ * L_) / B_;
    if (Tll <= 0 || (Tll * B_ + (long long)2 * B_ * L_) != os) {
        Tll = os / B_;
        write_mulv = 0;
    }
    int T = (int)Tll;

    pack_enc<<<(KE * G4 + 255) / 256, 256>>>(W_ih_e, W_hh_e);
    pack_dec<<<(KD * G4 + 255) / 256, 256>>>(W_hh_d);
    vae_main<<<NBLK, NT>>>(src, eps, b_e, W_mu, b_mu, W_lv, b_lv,
                           W_zh, b_zh, W_zc, b_zc, W_ih_d, b_d, W_out, b_out,
                           out, T, write_mulv);
}

// round 9
// speedup vs baseline: 1.0764x; 1.0708x over previous
#include <cuda_runtime.h>
#include <cuda_fp16.h>

// ---------------------------------------------------------------------------
// Seq2Seq VAE (encoder LSTM -> reparam -> autoregressive decoder LSTM)
// B=1024, T_src=1024, I=64, H=512, L=64, O=1, tgt_len derived from out_size.
//
// Round-7 result: fp16 weights gave only -0.5% vs fp32 -> NOT bytes-bound.
// Diagnosis: 2 warps/SMSP can't hide LDS/LDG/MUFU latency (stall exposure
// ~1.7x over the fma-pipe floor). This round: NT=512 (4 warps/SMSP), one
// feature per thread, f32x2 packed over the K dimension (fold .x+.y at end).
// Same 128 CTAs / 1 CTA/SM / fp16 weight stream; total fma work unchanged.
// ---------------------------------------------------------------------------

#define B_    1024
#define TSRC  1024
#define I_    64
#define H_    512
#define L_    64
#define G4    2048   // 4*H
#define KE    576    // I + H (encoder fused K)
#define KD    512    // decoder K (x handled as rank-1 epilogue fold)
#define MB    8      // batch rows per block
#define NT    512    // threads per block (= H features)
#define NBLK  (B_ / MB)
#define AS    592    // shA row stride (floats), 16B-multiple

// fp16 weights, packed [kpair][feature] cells of 8 halfs:
// cell(kp,f) = { (W[g*H+f][2kp], W[g*H+f][2kp+1]) : g=0..3 }  -> one uint4
__device__ uint4 g_WencH[(KE / 2) * H_];   // 2.36 MB
__device__ uint4 g_WdecH[(KD / 2) * H_];   // 2.10 MB

union U64 { unsigned long long u; float2 f; };
union UH  { uint4 u4; __half2 h2[4]; };

__device__ __forceinline__ unsigned long long ffma2(unsigned long long a,
                                                    unsigned long long b,
                                                    unsigned long long c) {
    unsigned long long d;
    asm("fma.rn.f32x2 %0, %1, %2, %3;" : "=l"(d) : "l"(a), "l"(b), "l"(c));
    return d;
}
__device__ __forceinline__ float sigf(float x)  { return 1.0f / (1.0f + __expf(-x)); }
__device__ __forceinline__ float tanh_f(float x){ return 2.0f / (1.0f + __expf(-2.0f * x)) - 1.0f; }

// acc[m][g] (f32x2 over k-parity) += shA[m][2i..2i+1] * W[2i..2i+1][g*H+f]
// 2-deep prefetch (~270 cyc cover vs L2 234-262).
template <int KP>
__device__ __forceinline__ void gemm2(const uint4* __restrict__ Wt,
                                      const float* __restrict__ shAf,
                                      int f, unsigned long long acc[MB][4]) {
    const uint4* wp = Wt + f;           // stride H_ uint4 per k-pair
    uint4 buf[2] = { wp[0], wp[H_] };
#pragma unroll 2
    for (int i = 0; i < KP; i++) {
        const int cur = i & 1;
        const int ip = (i + 2 < KP) ? (i + 2) : 0;
        uint4 nxt = wp[(size_t)ip * H_];

        UH u; u.u4 = buf[cur];
        U64 w[4];
#pragma unroll
        for (int g = 0; g < 4; g++) w[g].f = __half22float2(u.h2[g]);

#pragma unroll
        for (int m = 0; m < MB; m++) {
            U64 a;
            a.f = *reinterpret_cast<const float2*>(&shAf[m * AS + 2 * i]);
            acc[m][0] = ffma2(a.u, w[0].u, acc[m][0]);
            acc[m][1] = ffma2(a.u, w[1].u, acc[m][1]);
            acc[m][2] = ffma2(a.u, w[2].u, acc[m][2]);
            acc[m][3] = ffma2(a.u, w[3].u, acc[m][3]);
        }
        buf[cur] = nxt;
    }
}

// Pack: half_idx = ((kp*H + f)*4 + g)*2 + par ; value = W[g*H+f][2kp+par]
__global__ void pack_enc(const float* __restrict__ Wih, const float* __restrict__ Whh) {
    int idx = blockIdx.x * blockDim.x + threadIdx.x;
    if (idx >= KE * G4) return;
    int par = idx & 1, g = (idx >> 1) & 3, f = (idx >> 3) & (H_ - 1), kp = idx >> 12;
    int k = 2 * kp + par;
    int n = g * H_ + f;
    float v = (k < I_) ? Wih[n * I_ + k] : Whh[n * H_ + (k - I_)];
    reinterpret_cast<__half*>(g_WencH)[idx] = __float2half_rn(v);
}
__global__ void pack_dec(const float* __restrict__ Whh) {
    int idx = blockIdx.x * blockDim.x + threadIdx.x;
    if (idx >= KD * G4) return;
    int par = idx & 1, g = (idx >> 1) & 3, f = (idx >> 3) & (H_ - 1), kp = idx >> 12;
    int n = g * H_ + f;
    reinterpret_cast<__half*>(g_WdecH)[idx] = __float2half_rn(Whh[n * H_ + 2 * kp + par]);
}

__global__ void __launch_bounds__(NT, 1)
vae_main(const float* __restrict__ src, const float* __restrict__ eps,
         const float* __restrict__ b_e,
         const float* __restrict__ W_mu, const float* __restrict__ b_mu,
         const float* __restrict__ W_lv, const float* __restrict__ b_lv,
         const float* __restrict__ W_zh, const float* __restrict__ b_zh,
         const float* __restrict__ W_zc, const float* __restrict__ b_zc,
         const float* __restrict__ W_ih_d, const float* __restrict__ b_d,
         const float* __restrict__ W_out, const float* __restrict__ b_out,
         float* __restrict__ out, int T, int write_mulv) {
    // activations, scalar floats. enc: [0,64)=x_t, [64,576)=h. dec: [0,512)=h.
    __shared__ __align__(16) float shAf[MB * AS];
    __shared__ float shZ[MB][L_];
    __shared__ float shRed[16][MB];
    __shared__ float shX[MB];

    const int tid  = threadIdx.x;
    const int lane = tid & 31, warp = tid >> 5;
    const int f    = tid;             // feature index 0..511
    const int m0   = blockIdx.x * MB;

    // per-feature constants (gate-major rows g*H+f)
    float bev[4], bdv[4], wihdv[4];
#pragma unroll
    for (int g = 0; g < 4; g++) {
        bev[g]   = b_e[g * H_ + f];
        bdv[g]   = b_d[g * H_ + f];
        wihdv[g] = W_ih_d[g * H_ + f];
    }
    float wo = W_out[f];
    float bo = b_out[0];

    // h0 = c0 = 0
    for (int e = tid; e < MB * KE; e += NT) {
        int m = e / KE, k = e - m * KE;
        shAf[m * AS + k] = 0.f;
    }
    float cst[MB];
#pragma unroll
    for (int m = 0; m < MB; m++) cst[m] = 0.f;
    __syncthreads();

    // ---------------- Encoder ----------------
    for (int t = 0; t < TSRC; t++) {
        {   // x_t: 8 rows x 64 feats, one scalar per thread
            int m = tid >> 6, i = tid & 63;
            shAf[m * AS + i] = src[((size_t)(m0 + m) * TSRC + t) * I_ + i];
        }
        __syncthreads();   // x(t) and h(t-1) visible

        unsigned long long acc[MB][4];
#pragma unroll
        for (int m = 0; m < MB; m++)
            acc[m][0] = acc[m][1] = acc[m][2] = acc[m][3] = 0ull;
        gemm2<KE / 2>(g_WencH, shAf, f, acc);
        __syncthreads();   // reads done before h overwrite

#pragma unroll
        for (int m = 0; m < MB; m++) {
            U64 a0, a1, a2, a3;
            a0.u = acc[m][0]; a1.u = acc[m][1]; a2.u = acc[m][2]; a3.u = acc[m][3];
            float gi = a0.f.x + a0.f.y + bev[0];
            float gf = a1.f.x + a1.f.y + bev[1];
            float gg = a2.f.x + a2.f.y + bev[2];
            float go = a3.f.x + a3.f.y + bev[3];
            float c  = sigf(gf) * cst[m] + sigf(gi) * tanh_f(gg);
            cst[m] = c;
            shAf[m * AS + I_ + f] = sigf(go) * tanh_f(c);
        }
        // next iter: x-store hits disjoint region; its sync orders h writes too
    }
    __syncthreads();

    // ---------------- mu / logvar / z (512 tasks = 1/thread) ----------------
    {
        int m = tid >> 6, l = tid & 63;
        float smu = b_mu[l], slv = b_lv[l];
        for (int j = 0; j < H_; j += 4) {
            float4 wm = *reinterpret_cast<const float4*>(&W_mu[l * H_ + j]);
            float4 wl = *reinterpret_cast<const float4*>(&W_lv[l * H_ + j]);
            float h0 = shAf[m * AS + I_ + j],     h1 = shAf[m * AS + I_ + j + 1];
            float h2 = shAf[m * AS + I_ + j + 2], h3 = shAf[m * AS + I_ + j + 3];
            smu += h0 * wm.x + h1 * wm.y + h2 * wm.z + h3 * wm.w;
            slv += h0 * wl.x + h1 * wl.y + h2 * wl.z + h3 * wl.w;
        }
        float ev = eps[(size_t)(m0 + m) * L_ + l];
        shZ[m][l] = smu + ev * __expf(0.5f * slv);
        if (write_mulv) {
            size_t mu_off = (size_t)B_ * T;
            out[mu_off + (size_t)(m0 + m) * L_ + l] = smu;
            out[mu_off + (size_t)B_ * L_ + (size_t)(m0 + m) * L_ + l] = slv;
        }
    }
    __syncthreads();

    // ---------------- decoder init ----------------
    {
        for (int m = 0; m < MB; m++) {
            float ah = b_zh[f], ac = b_zc[f];
            for (int l = 0; l < L_; l++) {
                float zv = shZ[m][l];
                ah += zv * W_zh[f * L_ + l];
                ac += zv * W_zc[f * L_ + l];
            }
            shAf[m * AS + f] = tanh_f(ah);
            cst[m] = tanh_f(ac);
        }
        if (tid < MB) shX[tid] = 0.f;   // x_0 = 0
    }
    __syncthreads();

    // ---------------- Decoder (autoregressive) ----------------
    for (int t = 0; t < T; t++) {
        unsigned long long acc[MB][4];
#pragma unroll
        for (int m = 0; m < MB; m++)
            acc[m][0] = acc[m][1] = acc[m][2] = acc[m][3] = 0ull;
        gemm2<KD / 2>(g_WdecH, shAf, f, acc);
        __syncthreads();   // reads done before h overwrite

        float pm[MB];
#pragma unroll
        for (int m = 0; m < MB; m++) {
            float xv = shX[m];
            U64 a0, a1, a2, a3;
            a0.u = acc[m][0]; a1.u = acc[m][1]; a2.u = acc[m][2]; a3.u = acc[m][3];
            float gi = a0.f.x + a0.f.y + bdv[0] + xv * wihdv[0];
            float gf = a1.f.x + a1.f.y + bdv[1] + xv * wihdv[1];
            float gg = a2.f.x + a2.f.y + bdv[2] + xv * wihdv[2];
            float go = a3.f.x + a3.f.y + bdv[3] + xv * wihdv[3];
            float c  = sigf(gf) * cst[m] + sigf(gi) * tanh_f(gg);
            cst[m] = c;
            float h  = sigf(go) * tanh_f(c);
            shAf[m * AS + f] = h;
            pm[m] = h * wo;
        }
        // out_t = h . W_out + b_out : 16-warp reduction
#pragma unroll
        for (int m = 0; m < MB; m++) {
            float s = pm[m];
            s += __shfl_xor_sync(0xffffffffu, s, 16);
            s += __shfl_xor_sync(0xffffffffu, s, 8);
            s += __shfl_xor_sync(0xffffffffu, s, 4);
            s += __shfl_xor_sync(0xffffffffu, s, 2);
            s += __shfl_xor_sync(0xffffffffu, s, 1);
            if (lane == 0) shRed[warp][m] = s;
        }
        __syncthreads();
        if (tid < MB) {
            float s = bo;
#pragma unroll
            for (int w = 0; w < 16; w++) s += shRed[w][tid];
            out[(size_t)(m0 + tid) * T + t] = s;   // recon[b][t][0]
            shX[tid] = s;                          // feed back
        }
        __syncthreads();
    }
}

extern "C" void kernel_launch(void* const* d_in, const int* in_sizes, int n_in,
                              void* d_out, int out_size) {
    const float* src    = (const float*)d_in[0];
    const float* eps    = (const float*)d_in[1];
    // d_in[2] = tgt_len (int32 on device); length derived from out_size instead
    const float* W_ih_e = (const float*)d_in[3];
    const float* W_hh_e = (const float*)d_in[4];
    const float* b_e    = (const float*)d_in[5];
    const float* W_mu   = (const float*)d_in[6];
    const float* b_mu   = (const float*)d_in[7];
    const float* W_lv   = (const float*)d_in[8];
    const float* b_lv   = (const float*)d_in[9];
    const float* W_zh   = (const float*)d_in[10];
    const float* b_zh   = (const float*)d_in[11];
    const float* W_zc   = (const float*)d_in[12];
    const float* b_zc   = (const float*)d_in[13];
    const float* W_ih_d = (const float*)d_in[14];
    const float* W_hh_d = (const float*)d_in[15];
    const float* b_d    = (const float*)d_in[16];
    const float* W_out  = (const float*)d_in[17];
    const float* b_out  = (const float*)d_in[18];
    float* out = (float*)d_out;

    // out = [recon (B*T), mu (B*L), logvar (B*L)] flattened (preferred),
    // or recon-only if out_size doesn't include the mu/logvar tail.
    long long os = out_size;
    int write_mulv = 1;
    long long Tll = (os - (long long)2 * B_ * L_) / B_;
    if (Tll <= 0 || (Tll * B_ + (long long)2 * B_ * L_) != os) {
        Tll = os / B_;
        write_mulv = 0;
    }
    int T = (int)Tll;

    pack_enc<<<(KE * G4 + 255) / 256, 256>>>(W_ih_e, W_hh_e);
    pack_dec<<<(KD * G4 + 255) / 256, 256>>>(W_hh_d);
    vae_main<<<NBLK, NT>>>(src, eps, b_e, W_mu, b_mu, W_lv, b_lv,
                           W_zh, b_zh, W_zc, b_zc, W_ih_d, b_d, W_out, b_out,
                           out, T, write_mulv);
}

// round 15
// speedup vs baseline: 1.0964x; 1.0185x over previous
#include <cuda_runtime.h>
#include <cuda_fp16.h>

// ---------------------------------------------------------------------------
// Seq2Seq VAE (encoder LSTM -> reparam -> autoregressive decoder LSTM)
// B=1024, T_src=1024, I=64, H=512, L=64, O=1, tgt_len derived from out_size.
//
// Round-13: round-10's double-buffer variant timed out (suspect: x-prefetch
// register live across the gemm pushing past the 128-reg cap -> hot-loop
// spills). This version keeps the double-buffered barrier reduction
// (encoder 1 sync/step, decoder 2 syncs/step) but loads x(t+1) AFTER the
// gemm (immediate load->store, no long-lived register). Hot-loop register
// pressure is now <= the round-9 kernel that passed at 117.0 ms.
// ---------------------------------------------------------------------------

#define B_    1024
#define TSRC  1024
#define I_    64
#define H_    512
#define L_    64
#define G4    2048   // 4*H
#define KE    576    // I + H (encoder fused K)
#define KD    512    // decoder K (x handled as rank-1 epilogue fold)
#define MB    8      // batch rows per block
#define NT    512    // threads per block (= H features)
#define NBLK  (B_ / MB)
#define AS2   1168   // floats per batch row: 2 buffers x 576 + 16 pad

// fp16 weights, packed [kpair][feature] cells of 8 halfs:
// cell(kp,f) = { (W[g*H+f][2kp], W[g*H+f][2kp+1]) : g=0..3 }  -> one uint4
__device__ uint4 g_WencH[(KE / 2) * H_];   // 2.36 MB
__device__ uint4 g_WdecH[(KD / 2) * H_];   // 2.10 MB

union U64 { unsigned long long u; float2 f; };
union UH  { uint4 u4; __half2 h2[4]; };

__device__ __forceinline__ unsigned long long ffma2(unsigned long long a,
                                                    unsigned long long b,
                                                    unsigned long long c) {
    unsigned long long d;
    asm("fma.rn.f32x2 %0, %1, %2, %3;" : "=l"(d) : "l"(a), "l"(b), "l"(c));
    return d;
}
__device__ __forceinline__ float sigf(float x)  { return 1.0f / (1.0f + __expf(-x)); }
__device__ __forceinline__ float tanh_f(float x){ return 2.0f / (1.0f + __expf(-2.0f * x)) - 1.0f; }

// acc[m][g] (f32x2 over k-parity) += A[m][2i..2i+1] * W[2i..2i+1][g*H+f]
// A = base of m=0 row at k=0 (row stride AS2 floats). 2-deep prefetch.
template <int KP>
__device__ __forceinline__ void gemm2(const uint4* __restrict__ Wt,
                                      const float* __restrict__ A,
                                      int f, unsigned long long acc[MB][4]) {
    const uint4* wp = Wt + f;           // stride H_ uint4 per k-pair
    uint4 buf[2] = { wp[0], wp[H_] };
#pragma unroll 2
    for (int i = 0; i < KP; i++) {
        const int cur = i & 1;
        const int ip = (i + 2 < KP) ? (i + 2) : 0;
        uint4 nxt = wp[(size_t)ip * H_];

        UH u; u.u4 = buf[cur];
        U64 w[4];
#pragma unroll
        for (int g = 0; g < 4; g++) w[g].f = __half22float2(u.h2[g]);

#pragma unroll
        for (int m = 0; m < MB; m++) {
            U64 a;
            a.f = *reinterpret_cast<const float2*>(&A[m * AS2 + 2 * i]);
            acc[m][0] = ffma2(a.u, w[0].u, acc[m][0]);
            acc[m][1] = ffma2(a.u, w[1].u, acc[m][1]);
            acc[m][2] = ffma2(a.u, w[2].u, acc[m][2]);
            acc[m][3] = ffma2(a.u, w[3].u, acc[m][3]);
        }
        buf[cur] = nxt;
    }
}

// Pack: half_idx = ((kp*H + f)*4 + g)*2 + par ; value = W[g*H+f][2kp+par]
__global__ void pack_enc(const float* __restrict__ Wih, const float* __restrict__ Whh) {
    int idx = blockIdx.x * blockDim.x + threadIdx.x;
    if (idx >= KE * G4) return;
    int par = idx & 1, g = (idx >> 1) & 3, f = (idx >> 3) & (H_ - 1), kp = idx >> 12;
    int k = 2 * kp + par;
    int n = g * H_ + f;
    float v = (k < I_) ? Wih[n * I_ + k] : Whh[n * H_ + (k - I_)];
    reinterpret_cast<__half*>(g_WencH)[idx] = __float2half_rn(v);
}
__global__ void pack_dec(const float* __restrict__ Whh) {
    int idx = blockIdx.x * blockDim.x + threadIdx.x;
    if (idx >= KD * G4) return;
    int par = idx & 1, g = (idx >> 1) & 3, f = (idx >> 3) & (H_ - 1), kp = idx >> 12;
    int n = g * H_ + f;
    reinterpret_cast<__half*>(g_WdecH)[idx] = __float2half_rn(Whh[n * H_ + 2 * kp + par]);
}

__global__ void __launch_bounds__(NT, 1)
vae_main(const float* __restrict__ src, const float* __restrict__ eps,
         const float* __restrict__ b_e,
         const float* __restrict__ W_mu, const float* __restrict__ b_mu,
         const float* __restrict__ W_lv, const float* __restrict__ b_lv,
         const float* __restrict__ W_zh, const float* __restrict__ b_zh,
         const float* __restrict__ W_zc, const float* __restrict__ b_zc,
         const float* __restrict__ W_ih_d, const float* __restrict__ b_d,
         const float* __restrict__ W_out, const float* __restrict__ b_out,
         float* __restrict__ out, int T, int write_mulv) {
    // Double-buffered activations per batch row:
    // buf b at [b*576, b*576+576): [0,64)=x, [64,576)=h.
    __shared__ __align__(16) float shAf[MB * AS2];   // 37376 B
    __shared__ float shZ[MB][L_];
    __shared__ float shRed[16][MB];
    __shared__ float shX[MB];

    const int tid  = threadIdx.x;
    const int lane = tid & 31, warp = tid >> 5;
    const int f    = tid;             // feature index 0..511
    const int m0   = blockIdx.x * MB;

    // per-feature constants (gate-major rows g*H+f)
    float bev[4], bdv[4], wihdv[4];
#pragma unroll
    for (int g = 0; g < 4; g++) {
        bev[g]   = b_e[g * H_ + f];
        bdv[g]   = b_d[g * H_ + f];
        wihdv[g] = W_ih_d[g * H_ + f];
    }
    float wo = W_out[f];
    float bo = b_out[0];

    // Prologue: h(0)=0 into buf0 h-region; x(0) into buf0 x-region (disjoint)
    for (int e = tid; e < MB * H_; e += NT) {
        int m = e >> 9, k = e & (H_ - 1);
        shAf[m * AS2 + 64 + k] = 0.f;
    }
    {
        int m = tid >> 6, i = tid & 63;
        shAf[m * AS2 + i] = src[(size_t)(m0 + m) * TSRC * I_ + i];
    }
    float cst[MB];
#pragma unroll
    for (int m = 0; m < MB; m++) cst[m] = 0.f;
    __syncthreads();

    // ---------------- Encoder: ONE sync per step ----------------
    int cur = 0;
    for (int t = 0; t < TSRC; t++) {
        const int nxt = cur ^ 1;

        unsigned long long acc[MB][4];
#pragma unroll
        for (int m = 0; m < MB; m++)
            acc[m][0] = acc[m][1] = acc[m][2] = acc[m][3] = 0ull;
        gemm2<KE / 2>(g_WencH, shAf + cur * 576, f, acc);

        // x(t+1) into next buffer (load AFTER gemm: no long-lived register)
        {
            const int mx = tid >> 6, ix = tid & 63;
            float xv = 0.f;
            if (t + 1 < TSRC)
                xv = src[((size_t)(m0 + mx) * TSRC + (t + 1)) * I_ + ix];
            shAf[mx * AS2 + nxt * 576 + ix] = xv;
        }

        // epilogue writes h(t+1) into the OTHER buffer — no barrier needed
#pragma unroll
        for (int m = 0; m < MB; m++) {
            U64 a0, a1, a2, a3;
            a0.u = acc[m][0]; a1.u = acc[m][1]; a2.u = acc[m][2]; a3.u = acc[m][3];
            float gi = a0.f.x + a0.f.y + bev[0];
            float gf = a1.f.x + a1.f.y + bev[1];
            float gg = a2.f.x + a2.f.y + bev[2];
            float go = a3.f.x + a3.f.y + bev[3];
            float c  = sigf(gf) * cst[m] + sigf(gi) * tanh_f(gg);
            cst[m] = c;
            shAf[m * AS2 + nxt * 576 + 64 + f] = sigf(go) * tanh_f(c);
        }
        __syncthreads();                        // next buffer complete
        cur = nxt;
    }
    // final h is in buf[cur]

    // ---------------- mu / logvar / z (512 tasks = 1/thread) ----------------
    {
        int m = tid >> 6, l = tid & 63;
        float smu = b_mu[l], slv = b_lv[l];
        const float* hrow = &shAf[m * AS2 + cur * 576 + 64];
        for (int j = 0; j < H_; j += 4) {
            float4 wm = *reinterpret_cast<const float4*>(&W_mu[l * H_ + j]);
            float4 wl = *reinterpret_cast<const float4*>(&W_lv[l * H_ + j]);
            float h0 = hrow[j], h1 = hrow[j + 1], h2 = hrow[j + 2], h3 = hrow[j + 3];
            smu += h0 * wm.x + h1 * wm.y + h2 * wm.z + h3 * wm.w;
            slv += h0 * wl.x + h1 * wl.y + h2 * wl.z + h3 * wl.w;
        }
        float ev = eps[(size_t)(m0 + m) * L_ + l];
        shZ[m][l] = smu + ev * __expf(0.5f * slv);
        if (write_mulv) {
            size_t mu_off = (size_t)B_ * T;
            out[mu_off + (size_t)(m0 + m) * L_ + l] = smu;
            out[mu_off + (size_t)B_ * L_ + (size_t)(m0 + m) * L_ + l] = slv;
        }
    }
    __syncthreads();   // shZ ready; also all reads of encoder h done

    // ---------------- decoder init ----------------
    {
        for (int m = 0; m < MB; m++) {
            float ah = b_zh[f], ac = b_zc[f];
            for (int l = 0; l < L_; l++) {
                float zv = shZ[m][l];
                ah += zv * W_zh[f * L_ + l];
                ac += zv * W_zc[f * L_ + l];
            }
            shAf[m * AS2 + 64 + f] = tanh_f(ah);   // h_d into buf0
            cst[m] = tanh_f(ac);
        }
        if (tid < MB) shX[tid] = 0.f;   // x_0 = 0
    }
    __syncthreads();

    // ---------------- Decoder: TWO syncs per step ----------------
    int dc = 0;
    for (int t = 0; t < T; t++) {
        const int dn = dc ^ 1;
        unsigned long long acc[MB][4];
#pragma unroll
        for (int m = 0; m < MB; m++)
            acc[m][0] = acc[m][1] = acc[m][2] = acc[m][3] = 0ull;
        gemm2<KD / 2>(g_WdecH, shAf + dc * 576 + 64, f, acc);

        float pm[MB];
#pragma unroll
        for (int m = 0; m < MB; m++) {
            float xv = shX[m];
            U64 a0, a1, a2, a3;
            a0.u = acc[m][0]; a1.u = acc[m][1]; a2.u = acc[m][2]; a3.u = acc[m][3];
            float gi = a0.f.x + a0.f.y + bdv[0] + xv * wihdv[0];
            float gf = a1.f.x + a1.f.y + bdv[1] + xv * wihdv[1];
            float gg = a2.f.x + a2.f.y + bdv[2] + xv * wihdv[2];
            float go = a3.f.x + a3.f.y + bdv[3] + xv * wihdv[3];
            float c  = sigf(gf) * cst[m] + sigf(gi) * tanh_f(gg);
            cst[m] = c;
            float h  = sigf(go) * tanh_f(c);
            shAf[m * AS2 + dn * 576 + 64 + f] = h;   // other buffer
            pm[m] = h * wo;
        }
        // out_t = h . W_out + b_out : 16-warp reduction
#pragma unroll
        for (int m = 0; m < MB; m++) {
            float s = pm[m];
            s += __shfl_xor_sync(0xffffffffu, s, 16);
            s += __shfl_xor_sync(0xffffffffu, s, 8);
            s += __shfl_xor_sync(0xffffffffu, s, 4);
            s += __shfl_xor_sync(0xffffffffu, s, 2);
            s += __shfl_xor_sync(0xffffffffu, s, 1);
            if (lane == 0) shRed[warp][m] = s;
        }
        __syncthreads();   // shRed complete (h[dn] also complete)
        if (tid < MB) {
            float s = bo;
#pragma unroll
            for (int w = 0; w < 16; w++) s += shRed[w][tid];
            out[(size_t)(m0 + tid) * T + t] = s;   // recon[b][t][0]
            shX[tid] = s;                          // feed back
        }
        __syncthreads();   // shX visible; shRed reusable
        dc = dn;
    }
}

extern "C" void kernel_launch(void* const* d_in, const int* in_sizes, int n_in,
                              void* d_out, int out_size) {
    const float* src    = (const float*)d_in[0];
    const float* eps    = (const float*)d_in[1];
    // d_in[2] = tgt_len (int32 on device); length derived from out_size instead
    const float* W_ih_e = (const float*)d_in[3];
    const float* W_hh_e = (const float*)d_in[4];
    const float* b_e    = (const float*)d_in[5];
    const float* W_mu   = (const float*)d_in[6];
    const float* b_mu   = (const float*)d_in[7];
    const float* W_lv   = (const float*)d_in[8];
    const float* b_lv   = (const float*)d_in[9];
    const float* W_zh   = (const float*)d_in[10];
    const float* b_zh   = (const float*)d_in[11];
    const float* W_zc   = (const float*)d_in[12];
    const float* b_zc   = (const float*)d_in[13];
    const float* W_ih_d = (const float*)d_in[14];
    const float* W_hh_d = (const float*)d_in[15];
    const float* b_d    = (const float*)d_in[16];
    const float* W_out  = (const float*)d_in[17];
    const float* b_out  = (const float*)d_in[18];
    float* out = (float*)d_out;

    // out = [recon (B*T), mu (B*L), logvar (B*L)] flattened (preferred),
    // or recon-only if out_size doesn't include the mu/logvar tail.
    long long os = out_size;
    int write_mulv = 1;
    long long Tll = (os - (long long)2 * B_ * L_) / B_;
    if (Tll <= 0 || (Tll * B_ + (long long)2 * B_ * L_) != os) {
        Tll = os / B_;
        write_mulv = 0;
    }
    int T = (int)Tll;

    pack_enc<<<(KE * G4 + 255) / 256, 256>>>(W_ih_e, W_hh_e);
    pack_dec<<<(KD * G4 + 255) / 256, 256>>>(W_hh_d);
    vae_main<<<NBLK, NT>>>(src, eps, b_e, W_mu, b_mu, W_lv, b_lv,
                           W_zh, b_zh, W_zc, b_zc, W_ih_d, b_d, W_out, b_out,
                           out, T, write_mulv);
}